// round 13
// baseline (speedup 1.0000x reference)
#include <cuda_runtime.h>
#include <cuda_fp16.h>
#include <math.h>
#include <cstdint>

#define ALPHA   0.2f
#define NEG_INF -9e15f

static constexpr int Bc = 4;
static constexpr int Nc = 4096;
static constexpr int Dc = 256;
static constexpr int Rc = Bc * Nc;   // 16384 total rows

// ---------------- scratch (static device globals; no allocation) -------------
__device__ float g_w1[Dc];
__device__ float g_w2[Dc];
__device__ float g_Ax[Rc];
__device__ float g_Ay[Rc];
__device__ float g_Ex[Rc];    // exp(Ax)
__device__ float g_Ex2[Rc];   // exp(0.2*Ax)
__device__ float g_eyP[Rc];   // exp(Ay - c)
__device__ float g_eyN[Rc];   // exp(0.2*Ay - c)
// FW = feat @ W, stored TRANSPOSED per batch as [d][j], split fp16 hi/lo
__device__ __half g_FWh[(size_t)Bc * Dc * Nc];
__device__ __half g_FWl[(size_t)Bc * Dc * Nc];

// ====================== warp MMA helpers =====================================
__device__ __forceinline__ uint32_t smem_u32(const void* p) {
    uint32_t a;
    asm("{ .reg .u64 t; cvta.to.shared.u64 t, %1; cvt.u32.u64 %0, t; }" : "=r"(a) : "l"(p));
    return a;
}
__device__ __forceinline__ void ldmx4(uint32_t* r, uint32_t addr) {
    asm volatile("ldmatrix.sync.aligned.m8n8.x4.shared.b16 {%0,%1,%2,%3}, [%4];"
        : "=r"(r[0]), "=r"(r[1]), "=r"(r[2]), "=r"(r[3]) : "r"(addr));
}
__device__ __forceinline__ void mma16816(float* d, const uint32_t* a, const uint32_t* b) {
    asm volatile("mma.sync.aligned.m16n8k16.row.col.f32.f16.f16.f32 "
        "{%0,%1,%2,%3}, {%4,%5,%6,%7}, {%8,%9}, {%0,%1,%2,%3};"
        : "+f"(d[0]), "+f"(d[1]), "+f"(d[2]), "+f"(d[3])
        : "r"(a[0]), "r"(a[1]), "r"(a[2]), "r"(a[3]), "r"(b[0]), "r"(b[1]));
}
__device__ __forceinline__ void cp16(uint32_t dst, const void* src) {
    asm volatile("cp.async.cg.shared.global [%0], [%1], 16;" :: "r"(dst), "l"(src));
}
#define CP_COMMIT() asm volatile("cp.async.commit_group;" ::: "memory")
#define CP_WAIT0()  asm volatile("cp.async.wait_group 0;" ::: "memory")

// ---------------- kernel 1: w1 = W @ a1, w2 = W @ a2 -------------------------
__global__ void prep_kernel(const float* __restrict__ W,
                            const float* __restrict__ a1,
                            const float* __restrict__ a2) {
    int k = threadIdx.x;
    float s1 = 0.f, s2 = 0.f;
    const float* wrow = W + (size_t)k * Dc;
    for (int d = 0; d < Dc; d++) {
        float w = wrow[d];
        s1 += w * a1[d];
        s2 += w * a2[d];
    }
    g_w1[k] = s1;
    g_w2[k] = s2;
}

// ------- kernel 2: Ax, Ay, and column exps Ex=e^Ax, Ex2=e^{0.2Ax} ------------
__global__ void axay_kernel(const float* __restrict__ feat) {
    __shared__ float w1s[Dc], w2s[Dc];
    int t = threadIdx.x;
    w1s[t] = g_w1[t];
    w2s[t] = g_w2[t];
    __syncthreads();
    int warp = t >> 5, lane = t & 31;
    int row = blockIdx.x * 8 + warp;
    const float* f = feat + (size_t)row * Dc;
    float s1 = 0.f, s2 = 0.f;
    for (int d = lane; d < Dc; d += 32) {
        float v = f[d];
        s1 += v * w1s[d];
        s2 += v * w2s[d];
    }
    for (int o = 16; o; o >>= 1) {
        s1 += __shfl_xor_sync(0xffffffffu, s1, o);
        s2 += __shfl_xor_sync(0xffffffffu, s2, o);
    }
    if (lane == 0) {
        g_Ax[row]  = s1;
        g_Ay[row]  = s2;
        g_Ex[row]  = __expf(s1);
        g_Ex2[row] = __expf(ALPHA * s1);
    }
}

// ---------------- kernel 3: exp-free softmax stats ---------------------------
__global__ void stats_kernel(const int* __restrict__ adj) {
    int row = blockIdx.x;
    int b = row >> 12;
    const int*   arow = adj   + (size_t)row * Nc;
    const float* Axb  = g_Ax  + b * Nc;
    const float* Exb  = g_Ex  + b * Nc;
    const float* Ex2b = g_Ex2 + b * Nc;
    float ay   = g_Ay[row];
    float tneg = -ay;
    int t = threadIdx.x;

    float mx = NEG_INF, s1 = 0.f, s2 = 0.f;
#pragma unroll
    for (int k = 0; k < 4; k++) {
        int j = (t + k * 256) * 4;
        int4   a   = *(const int4*)  &arow[j];
        float4 ax  = *(const float4*)&Axb[j];
        float4 ex  = *(const float4*)&Exb[j];
        float4 ex2 = *(const float4*)&Ex2b[j];
        if (a.x > 0) { mx = fmaxf(mx, ax.x); if (ax.x > tneg) s1 += ex.x; else s2 += ex2.x; }
        if (a.y > 0) { mx = fmaxf(mx, ax.y); if (ax.y > tneg) s1 += ex.y; else s2 += ex2.y; }
        if (a.z > 0) { mx = fmaxf(mx, ax.z); if (ax.z > tneg) s1 += ex.z; else s2 += ex2.z; }
        if (a.w > 0) { mx = fmaxf(mx, ax.w); if (ax.w > tneg) s1 += ex.w; else s2 += ex2.w; }
    }
    for (int o = 16; o; o >>= 1) {
        mx = fmaxf(mx, __shfl_xor_sync(0xffffffffu, mx, o));
        s1 += __shfl_xor_sync(0xffffffffu, s1, o);
        s2 += __shfl_xor_sync(0xffffffffu, s2, o);
    }
    __shared__ float ms_[8], s1s_[8], s2s_[8];
    int warp = t >> 5, lane = t & 31;
    if (lane == 0) { ms_[warp] = mx; s1s_[warp] = s1; s2s_[warp] = s2; }
    __syncthreads();
    if (warp == 0) {
        mx = lane < 8 ? ms_[lane]  : NEG_INF;
        s1 = lane < 8 ? s1s_[lane] : 0.f;
        s2 = lane < 8 ? s2s_[lane] : 0.f;
        for (int o = 4; o; o >>= 1) {
            mx = fmaxf(mx, __shfl_xor_sync(0xffffffffu, mx, o));
            s1 += __shfl_xor_sync(0xffffffffu, s1, o);
            s2 += __shfl_xor_sync(0xffffffffu, s2, o);
        }
        if (lane == 0) {
            float m = mx + ay;
            m = m > 0.f ? m : ALPHA * m;
            float s = __expf(ay - m) * s1 + __expf(ALPHA * ay - m) * s2;
            float c = m + __logf(s);
            g_eyP[row] = __expf(ay - c);
            g_eyN[row] = __expf(ALPHA * ay - c);
        }
    }
}

// ---- kernel 4: FW = feat @ W, stored transposed [b][d][j] as fp16 hi/lo -----
__global__ __launch_bounds__(256, 2) void fw_kernel(const float* __restrict__ feat,
                                                    const float* __restrict__ W) {
    __shared__ float p_s[32][132];
    __shared__ float f_s[32][128];
    int t = threadIdx.x;
    int d0   = blockIdx.x * 128;
    int row0 = blockIdx.y * 128;
    int b    = row0 >> 12;
    int i0b  = row0 & (Nc - 1);
    int tx = t & 15, ty = t >> 4;
    int gj4 = t & 7, gi = t >> 3;

    float2 acc[8][4];
#pragma unroll
    for (int u = 0; u < 8; u++)
#pragma unroll
        for (int v = 0; v < 4; v++) acc[u][v] = make_float2(0.f, 0.f);

    for (int k0 = 0; k0 < Dc; k0 += 32) {
#pragma unroll
        for (int k = 0; k < 4; k++) {
            int q = t + k * 256, jl = q >> 5, d4 = q & 31;
            *(float4*)&f_s[jl][d4 * 4] = *(const float4*)&W[(size_t)(k0 + jl) * Dc + d0 + d4 * 4];
        }
#pragma unroll
        for (int k = 0; k < 4; k++) {
            int il = gi + k * 32;
            float4 h4 = *(const float4*)&feat[(size_t)(row0 + il) * Dc + k0 + gj4 * 4];
            p_s[gj4 * 4 + 0][il] = h4.x;
            p_s[gj4 * 4 + 1][il] = h4.y;
            p_s[gj4 * 4 + 2][il] = h4.z;
            p_s[gj4 * 4 + 3][il] = h4.w;
        }
        __syncthreads();
#pragma unroll
        for (int j = 0; j < 32; j++) {
            float4 fA = *(float4*)&f_s[j][tx * 8];
            float4 fB = *(float4*)&f_s[j][tx * 8 + 4];
            float4 pA = *(float4*)&p_s[j][ty * 8];
            float4 pB = *(float4*)&p_s[j][ty * 8 + 4];
            float pr[8] = { pA.x, pA.y, pA.z, pA.w, pB.x, pB.y, pB.z, pB.w };
            float fv[8] = { fA.x, fA.y, fA.z, fA.w, fB.x, fB.y, fB.z, fB.w };
#pragma unroll
            for (int u = 0; u < 8; u++) {
                acc[u][0].x += pr[u] * fv[0]; acc[u][0].y += pr[u] * fv[1];
                acc[u][1].x += pr[u] * fv[2]; acc[u][1].y += pr[u] * fv[3];
                acc[u][2].x += pr[u] * fv[4]; acc[u][2].y += pr[u] * fv[5];
                acc[u][3].x += pr[u] * fv[6]; acc[u][3].y += pr[u] * fv[7];
            }
        }
        __syncthreads();
    }
    union Pack { __half h[8]; uint4 u; };
#pragma unroll
    for (int v = 0; v < 8; v++) {
        int d = d0 + tx * 8 + v;
        Pack ph, pl;
#pragma unroll
        for (int u = 0; u < 8; u++) {
            float x = (v & 1) ? acc[u][v >> 1].y : acc[u][v >> 1].x;
            __half h = __float2half_rn(x);
            float r = x - __half2float(h);
            ph.h[u] = h;
            pl.h[u] = __float2half_rn(r);
        }
        size_t idx = (((size_t)(b * Dc + d)) << 12) + i0b + ty * 8;
        *(uint4*)&g_FWh[idx] = ph.u;
        *(uint4*)&g_FWl[idx] = pl.u;
    }
}

// ---------------- kernel 5: mma.sync PV GEMM + ELU ---------------------------
// CTA: 64 rows x 256 cols, K=4096 in 32-chunks, double-buffered cp.async.
// 8 warps: 2(m) x 4(n), warp tile 32x64. 3-term fp16 split, fp32 accum.
// adj register-prefetch distance 2; Ax/Ex/Ex2 staged to smem with B.
static constexpr uint32_t PITCH  = 80;                 // 40 fp16/row, ldmatrix conflict-free
static constexpr uint32_t A_BUF  = 64 * PITCH;         // 5120
static constexpr uint32_t B_BUF  = 256 * PITCH;        // 20480
static constexpr uint32_t OFF_AH = 0;
static constexpr uint32_t OFF_AL = A_BUF;              // 5120
static constexpr uint32_t OFF_BH = 2 * A_BUF;          // 10240
static constexpr uint32_t OFF_BL = 2 * A_BUF + B_BUF;  // 30720
static constexpr uint32_t OFF_AX = 2 * A_BUF + 2 * B_BUF;   // 51200 (Ax|Ex|Ex2 x 32 floats)
static constexpr uint32_t ST_SZ  = OFF_AX + 384;            // 51584
static constexpr uint32_t SMEM_PV = 2 * ST_SZ;              // 103168

__global__ __launch_bounds__(256, 2) void pv_mma(const int* __restrict__ adj,
                                                 float* __restrict__ out) {
    extern __shared__ char smem[];
    uint32_t sb = smem_u32(smem);
    int t = threadIdx.x;
    int wid = t >> 5, lane = t & 31;
    int row0 = blockIdx.x * 64;
    int b    = row0 >> 12;

    int warp_m = wid & 1, warp_n = wid >> 1;
    int m0 = warp_m * 32, n0 = warp_n * 64;

    // P-generation mapping: 4 threads per row, 8 cols each
    int gi = t >> 2, jq = t & 3;
    int grow = row0 + gi;
    float tneg = -g_Ay[grow], eyP = g_eyP[grow], eyN = g_eyN[grow];
    const int* arow = adj + ((size_t)grow << 12);
    const float* Axg  = g_Ax  + (b << 12);
    const float* Exg  = g_Ex  + (b << 12);
    const float* E2g  = g_Ex2 + (b << 12);

    float acc[2][8][4];
#pragma unroll
    for (int mf = 0; mf < 2; mf++)
#pragma unroll
        for (int nb = 0; nb < 8; nb++)
#pragma unroll
            for (int r = 0; r < 4; r++) acc[mf][nb][r] = 0.f;

    // ldmatrix lane recipes
    int a_r = lane & 15, a_k = (lane >> 4) * 8;
    int b_n = (lane & 7) + ((lane >> 4) << 3), b_k = ((lane >> 3) & 1) * 8;

    // B staging mapping: 4x16B units per 64B row
    int unit = t & 3, dr0 = t >> 2;

    auto stageB = [&](uint32_t base, int j0) {
#pragma unroll
        for (int k = 0; k < 4; k++) {
            int d = dr0 + k * 64;
            uint32_t so = (uint32_t)d * PITCH + unit * 16;
            size_t src = (((size_t)(b * Dc + d)) << 12) + j0 + unit * 8;
            cp16(sb + base + OFF_BH + so, &g_FWh[src]);
            cp16(sb + base + OFF_BL + so, &g_FWl[src]);
        }
        if (t < 24) {   // stage Ax/Ex/Ex2 [j0..j0+32): 3 arrays x 8 x 16B
            int arr = t >> 3, u = t & 7;
            const float* srcs[3] = { Axg, Exg, E2g };
            cp16(sb + base + OFF_AX + arr * 128 + u * 16, srcs[arr] + j0 + u * 4);
        }
    };
    // convert + STS for chunk at j0 using pre-loaded adj regs; Ax/Ex/Ex2 from smem
    auto pgen = [&](uint32_t base, const int4* areg) {
        uint32_t hi[4], lo[4];
#pragma unroll
        for (int g = 0; g < 2; g++) {
            int jj = (jq * 8 + g * 4) * 4;   // byte offset within 32-float slice
            float4 ax4 = *(const float4*)(smem + base + OFF_AX +   0 + jj);
            float4 ex4 = *(const float4*)(smem + base + OFF_AX + 128 + jj);
            float4 e24 = *(const float4*)(smem + base + OFF_AX + 256 + jj);
            int4 a4 = areg[g];
            float p0 = a4.x > 0 ? (ax4.x > tneg ? ex4.x * eyP : e24.x * eyN) : 0.f;
            float p1 = a4.y > 0 ? (ax4.y > tneg ? ex4.y * eyP : e24.y * eyN) : 0.f;
            float p2 = a4.z > 0 ? (ax4.z > tneg ? ex4.z * eyP : e24.z * eyN) : 0.f;
            float p3 = a4.w > 0 ? (ax4.w > tneg ? ex4.w * eyP : e24.w * eyN) : 0.f;
            __half h0 = __float2half_rn(p0), h1 = __float2half_rn(p1);
            __half h2 = __float2half_rn(p2), h3 = __float2half_rn(p3);
            __half l0 = __float2half_rn(p0 - __half2float(h0));
            __half l1 = __float2half_rn(p1 - __half2float(h1));
            __half l2 = __float2half_rn(p2 - __half2float(h2));
            __half l3 = __float2half_rn(p3 - __half2float(h3));
            __half2 H0 = {h0, h1}, H1 = {h2, h3}, L0 = {l0, l1}, L1 = {l2, l3};
            hi[g * 2 + 0] = *(uint32_t*)&H0; hi[g * 2 + 1] = *(uint32_t*)&H1;
            lo[g * 2 + 0] = *(uint32_t*)&L0; lo[g * 2 + 1] = *(uint32_t*)&L1;
        }
        uint32_t so = (uint32_t)gi * PITCH + jq * 16;
        *(uint4*)(smem + base + OFF_AH + so) = make_uint4(hi[0], hi[1], hi[2], hi[3]);
        *(uint4*)(smem + base + OFF_AL + so) = make_uint4(lo[0], lo[1], lo[2], lo[3]);
    };
    auto domma = [&](uint32_t base) {
#pragma unroll
        for (int kk = 0; kk < 2; kk++) {
            uint32_t Ah[2][4], Al[2][4];
#pragma unroll
            for (int mf = 0; mf < 2; mf++) {
                uint32_t aaddr = sb + base + OFF_AH
                               + (uint32_t)(m0 + mf * 16 + a_r) * PITCH + (kk * 16 + a_k) * 2;
                ldmx4(Ah[mf], aaddr);
                ldmx4(Al[mf], aaddr + (OFF_AL - OFF_AH));
            }
#pragma unroll
            for (int nb = 0; nb < 4; nb++) {
                uint32_t baddr = sb + base + OFF_BH
                               + (uint32_t)(n0 + nb * 16 + b_n) * PITCH + (kk * 16 + b_k) * 2;
                uint32_t Bh[4], Bl[4];
                ldmx4(Bh, baddr);
                ldmx4(Bl, baddr + (OFF_BL - OFF_BH));
#pragma unroll
                for (int mf = 0; mf < 2; mf++) {
#pragma unroll
                    for (int nf = 0; nf < 2; nf++) {
                        mma16816(acc[mf][nb * 2 + nf], Ah[mf], Bh + nf * 2);
                        mma16816(acc[mf][nb * 2 + nf], Al[mf], Bh + nf * 2);
                        mma16816(acc[mf][nb * 2 + nf], Ah[mf], Bl + nf * 2);
                    }
                }
            }
        }
    };

    int4 areg[2][2];   // [parity of target chunk][g]
    auto load_adj = [&](int4* dst, int j0) {
        int jbase = j0 + jq * 8;
        dst[0] = *(const int4*)&arow[jbase];
        dst[1] = *(const int4*)&arow[jbase + 4];
    };

    // ---- prologue: chunk 0 ----
    stageB(0, 0);
    CP_COMMIT();
    load_adj(areg[0], 0);           // chunk 0 (parity 0)
    load_adj(areg[1], 32);          // chunk 1 (parity 1)
    CP_WAIT0();
    __syncthreads();                // AX slice visible
    pgen(0, areg[0]);
    __syncthreads();                // A tiles visible for MMA

    for (int c = 0; c < 128; c++) {
        uint32_t cur = (uint32_t)(c & 1) * ST_SZ;
        uint32_t nxt = (uint32_t)((c + 1) & 1) * ST_SZ;
        if (c < 127) {
            stageB(nxt, (c + 1) * 32);
            CP_COMMIT();
        }
        if (c < 126) load_adj(areg[c & 1], (c + 2) * 32);   // prefetch distance 2
        domma(cur);
        if (c < 127) {
            CP_WAIT0();                 // B + AX of nxt landed (during domma)
            pgen(nxt, areg[(c + 1) & 1]);
        }
        __syncthreads();
    }

    // ---- epilogue: ELU + store ----
    int r_base = row0 + m0 + (lane >> 2);
    int c_base = n0 + (lane & 3) * 2;
#pragma unroll
    for (int mf = 0; mf < 2; mf++) {
#pragma unroll
        for (int nb = 0; nb < 8; nb++) {
            float v0 = acc[mf][nb][0], v1 = acc[mf][nb][1];
            float v2 = acc[mf][nb][2], v3 = acc[mf][nb][3];
            v0 = v0 > 0.f ? v0 : expm1f(v0);
            v1 = v1 > 0.f ? v1 : expm1f(v1);
            v2 = v2 > 0.f ? v2 : expm1f(v2);
            v3 = v3 > 0.f ? v3 : expm1f(v3);
            int col = c_base + nb * 8;
            float* o0 = out + (size_t)(r_base + mf * 16) * Dc + col;
            float* o1 = out + (size_t)(r_base + mf * 16 + 8) * Dc + col;
            *(float2*)o0 = make_float2(v0, v1);
            *(float2*)o1 = make_float2(v2, v3);
        }
    }
}

// ---------------- launch ------------------------------------------------------
extern "C" void kernel_launch(void* const* d_in, const int* in_sizes, int n_in,
                              void* d_out, int out_size) {
    const float* feat = (const float*)d_in[0];
    const int*   adj  = (const int*)d_in[1];
    const float* W    = (const float*)d_in[2];
    const float* a1   = (const float*)d_in[3];
    const float* a2   = (const float*)d_in[4];
    float* out = (float*)d_out;

    cudaFuncSetAttribute(pv_mma, cudaFuncAttributeMaxDynamicSharedMemorySize, SMEM_PV);

    prep_kernel<<<1, 256>>>(W, a1, a2);
    axay_kernel<<<Rc / 8, 256>>>(feat);
    fw_kernel<<<dim3(Dc / 128, Rc / 128), 256>>>(feat, W);
    stats_kernel<<<Rc, 256>>>(adj);
    pv_mma<<<Rc / 64, 256, SMEM_PV>>>(adj, out);
}

// round 14
// speedup vs baseline: 1.1583x; 1.1583x over previous
#include <cuda_runtime.h>
#include <cuda_bf16.h>
#include <math.h>
#include <cstdint>

#define ALPHA   0.2f
#define NEG_INF -9e15f

static constexpr int Bc = 4;
static constexpr int Nc = 4096;
static constexpr int Dc = 256;
static constexpr int Rc = Bc * Nc;   // 16384 total rows

// ---------------- scratch (static device globals; no allocation) -------------
__device__ float g_Axp[2][Rc];   // Ax partials (one per d-half block)
__device__ float g_Ayp[2][Rc];
__device__ float g_Ax[Rc];
__device__ float g_Ay[Rc];
__device__ float g_Ex[Rc];    // exp(Ax)
__device__ float g_Ex2[Rc];   // exp(0.2*Ax)
__device__ float g_eyP[Rc];   // exp(Ay - c)
__device__ float g_eyN[Rc];   // exp(0.2*Ay - c)
// FW = feat @ W, stored TRANSPOSED per batch as [d][j], split bf16 hi/lo
__device__ __nv_bfloat16 g_FWh[(size_t)Bc * Dc * Nc];
__device__ __nv_bfloat16 g_FWl[(size_t)Bc * Dc * Nc];

// ====================== warp MMA helpers =====================================
__device__ __forceinline__ uint32_t smem_u32(const void* p) {
    uint32_t a;
    asm("{ .reg .u64 t; cvta.to.shared.u64 t, %1; cvt.u32.u64 %0, t; }" : "=r"(a) : "l"(p));
    return a;
}
__device__ __forceinline__ void ldmx4(uint32_t* r, uint32_t addr) {
    asm volatile("ldmatrix.sync.aligned.m8n8.x4.shared.b16 {%0,%1,%2,%3}, [%4];"
        : "=r"(r[0]), "=r"(r[1]), "=r"(r[2]), "=r"(r[3]) : "r"(addr));
}
__device__ __forceinline__ void mma16816(float* d, const uint32_t* a, const uint32_t* b) {
    asm volatile("mma.sync.aligned.m16n8k16.row.col.f32.bf16.bf16.f32 "
        "{%0,%1,%2,%3}, {%4,%5,%6,%7}, {%8,%9}, {%0,%1,%2,%3};"
        : "+f"(d[0]), "+f"(d[1]), "+f"(d[2]), "+f"(d[3])
        : "r"(a[0]), "r"(a[1]), "r"(a[2]), "r"(a[3]), "r"(b[0]), "r"(b[1]));
}
__device__ __forceinline__ void cp16(uint32_t dst, const void* src) {
    asm volatile("cp.async.cg.shared.global [%0], [%1], 16;" :: "r"(dst), "l"(src));
}
#define CP_COMMIT() asm volatile("cp.async.commit_group;" ::: "memory")
#define CP_WAIT0()  asm volatile("cp.async.wait_group 0;" ::: "memory")

// ---- kernel 1: FW = feat @ W -> transposed bf16 hi/lo + Ax/Ay partials ------
// Ax = FW @ a1, Ay = FW @ a2 accumulated per d-half (blockIdx.x), no atomics.
__global__ __launch_bounds__(256, 2) void fw_kernel(const float* __restrict__ feat,
                                                    const float* __restrict__ W,
                                                    const float* __restrict__ a1,
                                                    const float* __restrict__ a2) {
    __shared__ float p_s[32][132];
    __shared__ float f_s[32][128];
    int t = threadIdx.x;
    int bx   = blockIdx.x;
    int d0   = bx * 128;
    int row0 = blockIdx.y * 128;
    int b    = row0 >> 12;
    int i0b  = row0 & (Nc - 1);
    int tx = t & 15, ty = t >> 4;
    int gj4 = t & 7, gi = t >> 3;

    float2 acc[8][4];
#pragma unroll
    for (int u = 0; u < 8; u++)
#pragma unroll
        for (int v = 0; v < 4; v++) acc[u][v] = make_float2(0.f, 0.f);

    for (int k0 = 0; k0 < Dc; k0 += 32) {
#pragma unroll
        for (int k = 0; k < 4; k++) {
            int q = t + k * 256, jl = q >> 5, d4 = q & 31;
            *(float4*)&f_s[jl][d4 * 4] = *(const float4*)&W[(size_t)(k0 + jl) * Dc + d0 + d4 * 4];
        }
#pragma unroll
        for (int k = 0; k < 4; k++) {
            int il = gi + k * 32;
            float4 h4 = *(const float4*)&feat[(size_t)(row0 + il) * Dc + k0 + gj4 * 4];
            p_s[gj4 * 4 + 0][il] = h4.x;
            p_s[gj4 * 4 + 1][il] = h4.y;
            p_s[gj4 * 4 + 2][il] = h4.z;
            p_s[gj4 * 4 + 3][il] = h4.w;
        }
        __syncthreads();
#pragma unroll
        for (int j = 0; j < 32; j++) {
            float4 fA = *(float4*)&f_s[j][tx * 8];
            float4 fB = *(float4*)&f_s[j][tx * 8 + 4];
            float4 pA = *(float4*)&p_s[j][ty * 8];
            float4 pB = *(float4*)&p_s[j][ty * 8 + 4];
            float pr[8] = { pA.x, pA.y, pA.z, pA.w, pB.x, pB.y, pB.z, pB.w };
            float fv[8] = { fA.x, fA.y, fA.z, fA.w, fB.x, fB.y, fB.z, fB.w };
#pragma unroll
            for (int u = 0; u < 8; u++) {
                acc[u][0].x += pr[u] * fv[0]; acc[u][0].y += pr[u] * fv[1];
                acc[u][1].x += pr[u] * fv[2]; acc[u][1].y += pr[u] * fv[3];
                acc[u][2].x += pr[u] * fv[4]; acc[u][2].y += pr[u] * fv[5];
                acc[u][3].x += pr[u] * fv[6]; acc[u][3].y += pr[u] * fv[7];
            }
        }
        __syncthreads();
    }
    // ---- split to hi/lo bf16, store transposed FWt[b][d][i] ----
    union Pack { __nv_bfloat16 h[8]; uint4 u; };
#pragma unroll
    for (int v = 0; v < 8; v++) {
        int d = d0 + tx * 8 + v;
        Pack ph, pl;
#pragma unroll
        for (int u = 0; u < 8; u++) {
            float x = (v & 1) ? acc[u][v >> 1].y : acc[u][v >> 1].x;
            __nv_bfloat16 h = __float2bfloat16_rn(x);
            float r = x - __bfloat162float(h);
            ph.h[u] = h;
            pl.h[u] = __float2bfloat16_rn(r);
        }
        size_t idx = (((size_t)(b * Dc + d)) << 12) + i0b + ty * 8;
        *(uint4*)&g_FWh[idx] = ph.u;
        *(uint4*)&g_FWl[idx] = pl.u;
    }
    // ---- Ax/Ay partials: acc rows dotted with a1/a2 slice ----
    float a1v[8], a2v[8];
#pragma unroll
    for (int v = 0; v < 8; v++) { a1v[v] = a1[d0 + tx * 8 + v]; a2v[v] = a2[d0 + tx * 8 + v]; }
#pragma unroll
    for (int u = 0; u < 8; u++) {
        float r[8] = { acc[u][0].x, acc[u][0].y, acc[u][1].x, acc[u][1].y,
                       acc[u][2].x, acc[u][2].y, acc[u][3].x, acc[u][3].y };
        float sx = 0.f, sy = 0.f;
#pragma unroll
        for (int v = 0; v < 8; v++) { sx += r[v] * a1v[v]; sy += r[v] * a2v[v]; }
        // reduce across the 16 tx-lanes sharing this row (xor 1,2,4,8 stays in 16-group)
#pragma unroll
        for (int o = 1; o < 16; o <<= 1) {
            sx += __shfl_xor_sync(0xffffffffu, sx, o);
            sy += __shfl_xor_sync(0xffffffffu, sy, o);
        }
        if (tx == 0) {
            g_Axp[bx][row0 + ty * 8 + u] = sx;
            g_Ayp[bx][row0 + ty * 8 + u] = sy;
        }
    }
}

// ---- kernel 2: finalize Ax/Ay, compute Ex/Ex2 -------------------------------
__global__ void finalize_kernel() {
    int i = blockIdx.x * 256 + threadIdx.x;
    float ax = g_Axp[0][i] + g_Axp[1][i];
    float ay = g_Ayp[0][i] + g_Ayp[1][i];
    g_Ax[i]  = ax;
    g_Ay[i]  = ay;
    g_Ex[i]  = __expf(ax);
    g_Ex2[i] = __expf(ALPHA * ax);
}

// ---------------- kernel 3: exp-free softmax stats ---------------------------
__global__ void stats_kernel(const int* __restrict__ adj) {
    int row = blockIdx.x;
    int b = row >> 12;
    const int*   arow = adj   + (size_t)row * Nc;
    const float* Axb  = g_Ax  + b * Nc;
    const float* Exb  = g_Ex  + b * Nc;
    const float* Ex2b = g_Ex2 + b * Nc;
    float ay   = g_Ay[row];
    float tneg = -ay;
    int t = threadIdx.x;

    float mx = NEG_INF, s1 = 0.f, s2 = 0.f;
#pragma unroll
    for (int k = 0; k < 4; k++) {
        int j = (t + k * 256) * 4;
        int4   a   = *(const int4*)  &arow[j];
        float4 ax  = *(const float4*)&Axb[j];
        float4 ex  = *(const float4*)&Exb[j];
        float4 ex2 = *(const float4*)&Ex2b[j];
        if (a.x > 0) { mx = fmaxf(mx, ax.x); if (ax.x > tneg) s1 += ex.x; else s2 += ex2.x; }
        if (a.y > 0) { mx = fmaxf(mx, ax.y); if (ax.y > tneg) s1 += ex.y; else s2 += ex2.y; }
        if (a.z > 0) { mx = fmaxf(mx, ax.z); if (ax.z > tneg) s1 += ex.z; else s2 += ex2.z; }
        if (a.w > 0) { mx = fmaxf(mx, ax.w); if (ax.w > tneg) s1 += ex.w; else s2 += ex2.w; }
    }
    for (int o = 16; o; o >>= 1) {
        mx = fmaxf(mx, __shfl_xor_sync(0xffffffffu, mx, o));
        s1 += __shfl_xor_sync(0xffffffffu, s1, o);
        s2 += __shfl_xor_sync(0xffffffffu, s2, o);
    }
    __shared__ float ms_[8], s1s_[8], s2s_[8];
    int warp = t >> 5, lane = t & 31;
    if (lane == 0) { ms_[warp] = mx; s1s_[warp] = s1; s2s_[warp] = s2; }
    __syncthreads();
    if (warp == 0) {
        mx = lane < 8 ? ms_[lane]  : NEG_INF;
        s1 = lane < 8 ? s1s_[lane] : 0.f;
        s2 = lane < 8 ? s2s_[lane] : 0.f;
        for (int o = 4; o; o >>= 1) {
            mx = fmaxf(mx, __shfl_xor_sync(0xffffffffu, mx, o));
            s1 += __shfl_xor_sync(0xffffffffu, s1, o);
            s2 += __shfl_xor_sync(0xffffffffu, s2, o);
        }
        if (lane == 0) {
            float m = mx + ay;
            m = m > 0.f ? m : ALPHA * m;
            float s = __expf(ay - m) * s1 + __expf(ALPHA * ay - m) * s2;
            float c = m + __logf(s);
            g_eyP[row] = __expf(ay - c);
            g_eyN[row] = __expf(ALPHA * ay - c);
        }
    }
}

// ---------------- kernel 4: mma.sync PV GEMM + ELU ---------------------------
// CTA: 64 rows x 256 cols, K=4096 in 32-chunks, double-buffered + cp.async.
// 8 warps: 2(m) x 4(n), warp tile 32x64. 3-term bf16 split, fp32 accum.
static constexpr uint32_t PITCH  = 80;                 // 40 bf16/row, ldmatrix conflict-free
static constexpr uint32_t A_BUF  = 64 * PITCH;         // 5120
static constexpr uint32_t B_BUF  = 256 * PITCH;        // 20480
static constexpr uint32_t OFF_AH = 0;
static constexpr uint32_t OFF_AL = A_BUF;              // 5120
static constexpr uint32_t OFF_BH = 2 * A_BUF;          // 10240
static constexpr uint32_t OFF_BL = 2 * A_BUF + B_BUF;  // 30720
static constexpr uint32_t ST_SZ  = 2 * A_BUF + 2 * B_BUF;  // 51200
static constexpr uint32_t SMEM_PV = 2 * ST_SZ;             // 102400

__global__ __launch_bounds__(256, 2) void pv_mma(const int* __restrict__ adj,
                                                 float* __restrict__ out) {
    extern __shared__ char smem[];
    uint32_t sb = smem_u32(smem);
    int t = threadIdx.x;
    int wid = t >> 5, lane = t & 31;
    int row0 = blockIdx.x * 64;
    int b    = row0 >> 12;

    int warp_m = wid & 1, warp_n = wid >> 1;
    int m0 = warp_m * 32, n0 = warp_n * 64;

    // P-generation mapping: 4 threads per row, 8 cols each
    int gi = t >> 2, jq = t & 3;
    int grow = row0 + gi;
    float tneg = -g_Ay[grow], eyP = g_eyP[grow], eyN = g_eyN[grow];
    const int*   arow = adj   + ((size_t)grow << 12);
    const float* Axb  = g_Ax  + (b << 12);
    const float* Exb  = g_Ex  + (b << 12);
    const float* E2b  = g_Ex2 + (b << 12);

    float acc[2][8][4];
#pragma unroll
    for (int mf = 0; mf < 2; mf++)
#pragma unroll
        for (int nb = 0; nb < 8; nb++)
#pragma unroll
            for (int r = 0; r < 4; r++) acc[mf][nb][r] = 0.f;

    // ldmatrix lane recipes (validated)
    int a_r = lane & 15, a_k = (lane >> 4) * 8;
    int b_n = (lane & 7) + ((lane >> 4) << 3), b_k = ((lane >> 3) & 1) * 8;

    // B staging mapping: 4x16B units per 64B row
    int unit = t & 3, dr0 = t >> 2;

    auto stageB = [&](uint32_t base, int j0) {
#pragma unroll
        for (int k = 0; k < 4; k++) {
            int d = dr0 + k * 64;
            uint32_t so = (uint32_t)d * PITCH + unit * 16;
            size_t src = (((size_t)(b * Dc + d)) << 12) + j0 + unit * 8;
            cp16(sb + base + OFF_BH + so, &g_FWh[src]);
            cp16(sb + base + OFF_BL + so, &g_FWl[src]);
        }
    };
    auto pgen = [&](uint32_t base, int j0) {
        uint32_t hi[4], lo[4];
#pragma unroll
        for (int g = 0; g < 2; g++) {
            int j = j0 + jq * 8 + g * 4;
            int4   a4  = *(const int4*)  &arow[j];
            float4 ax4 = *(const float4*)&Axb[j];
            float4 ex4 = *(const float4*)&Exb[j];
            float4 e24 = *(const float4*)&E2b[j];
            float p0 = a4.x > 0 ? (ax4.x > tneg ? ex4.x * eyP : e24.x * eyN) : 0.f;
            float p1 = a4.y > 0 ? (ax4.y > tneg ? ex4.y * eyP : e24.y * eyN) : 0.f;
            float p2 = a4.z > 0 ? (ax4.z > tneg ? ex4.z * eyP : e24.z * eyN) : 0.f;
            float p3 = a4.w > 0 ? (ax4.w > tneg ? ex4.w * eyP : e24.w * eyN) : 0.f;
            __nv_bfloat16 h0 = __float2bfloat16_rn(p0), h1 = __float2bfloat16_rn(p1);
            __nv_bfloat16 h2 = __float2bfloat16_rn(p2), h3 = __float2bfloat16_rn(p3);
            __nv_bfloat16 l0 = __float2bfloat16_rn(p0 - __bfloat162float(h0));
            __nv_bfloat16 l1 = __float2bfloat16_rn(p1 - __bfloat162float(h1));
            __nv_bfloat16 l2 = __float2bfloat16_rn(p2 - __bfloat162float(h2));
            __nv_bfloat16 l3 = __float2bfloat16_rn(p3 - __bfloat162float(h3));
            __nv_bfloat162 H0 = {h0, h1}, H1 = {h2, h3}, L0 = {l0, l1}, L1 = {l2, l3};
            hi[g * 2 + 0] = *(uint32_t*)&H0; hi[g * 2 + 1] = *(uint32_t*)&H1;
            lo[g * 2 + 0] = *(uint32_t*)&L0; lo[g * 2 + 1] = *(uint32_t*)&L1;
        }
        uint32_t so = (uint32_t)gi * PITCH + jq * 16;
        *(uint4*)(smem + base + OFF_AH + so) = make_uint4(hi[0], hi[1], hi[2], hi[3]);
        *(uint4*)(smem + base + OFF_AL + so) = make_uint4(lo[0], lo[1], lo[2], lo[3]);
    };
    auto domma = [&](uint32_t base) {
#pragma unroll
        for (int kk = 0; kk < 2; kk++) {
            uint32_t Ah[2][4], Al[2][4];
#pragma unroll
            for (int mf = 0; mf < 2; mf++) {
                uint32_t aaddr = sb + base + OFF_AH
                               + (uint32_t)(m0 + mf * 16 + a_r) * PITCH + (kk * 16 + a_k) * 2;
                ldmx4(Ah[mf], aaddr);
                ldmx4(Al[mf], aaddr + (OFF_AL - OFF_AH));
            }
#pragma unroll
            for (int nb = 0; nb < 4; nb++) {
                uint32_t baddr = sb + base + OFF_BH
                               + (uint32_t)(n0 + nb * 16 + b_n) * PITCH + (kk * 16 + b_k) * 2;
                uint32_t Bh[4], Bl[4];
                ldmx4(Bh, baddr);
                ldmx4(Bl, baddr + (OFF_BL - OFF_BH));
#pragma unroll
                for (int mf = 0; mf < 2; mf++) {
#pragma unroll
                    for (int nf = 0; nf < 2; nf++) {
                        mma16816(acc[mf][nb * 2 + nf], Ah[mf], Bh + nf * 2);
                        mma16816(acc[mf][nb * 2 + nf], Al[mf], Bh + nf * 2);
                        mma16816(acc[mf][nb * 2 + nf], Ah[mf], Bl + nf * 2);
                    }
                }
            }
        }
    };

    // prologue: fill stage 0 with chunk 0
    stageB(0, 0);
    CP_COMMIT();
    pgen(0, 0);
    CP_WAIT0();
    __syncthreads();

    for (int c = 0; c < 128; c++) {
        uint32_t cur = (uint32_t)(c & 1) * ST_SZ;
        uint32_t nxt = (uint32_t)((c + 1) & 1) * ST_SZ;
        if (c < 127) {
            stageB(nxt, (c + 1) * 32);
            CP_COMMIT();
            pgen(nxt, (c + 1) * 32);
        }
        domma(cur);
        if (c < 127) CP_WAIT0();
        __syncthreads();
    }

    // ---- epilogue: ELU + store ----
    int r_base = row0 + m0 + (lane >> 2);
    int c_base = n0 + (lane & 3) * 2;
#pragma unroll
    for (int mf = 0; mf < 2; mf++) {
#pragma unroll
        for (int nb = 0; nb < 8; nb++) {
            float v0 = acc[mf][nb][0], v1 = acc[mf][nb][1];
            float v2 = acc[mf][nb][2], v3 = acc[mf][nb][3];
            v0 = v0 > 0.f ? v0 : expm1f(v0);
            v1 = v1 > 0.f ? v1 : expm1f(v1);
            v2 = v2 > 0.f ? v2 : expm1f(v2);
            v3 = v3 > 0.f ? v3 : expm1f(v3);
            int col = c_base + nb * 8;
            float* o0 = out + (size_t)(r_base + mf * 16) * Dc + col;
            float* o1 = out + (size_t)(r_base + mf * 16 + 8) * Dc + col;
            *(float2*)o0 = make_float2(v0, v1);
            *(float2*)o1 = make_float2(v2, v3);
        }
    }
}

// ---------------- launch ------------------------------------------------------
extern "C" void kernel_launch(void* const* d_in, const int* in_sizes, int n_in,
                              void* d_out, int out_size) {
    const float* feat = (const float*)d_in[0];
    const int*   adj  = (const int*)d_in[1];
    const float* W    = (const float*)d_in[2];
    const float* a1   = (const float*)d_in[3];
    const float* a2   = (const float*)d_in[4];
    float* out = (float*)d_out;

    cudaFuncSetAttribute(pv_mma, cudaFuncAttributeMaxDynamicSharedMemorySize, SMEM_PV);

    fw_kernel<<<dim3(2, Rc / 128), 256>>>(feat, W, a1, a2);
    finalize_kernel<<<Rc / 256, 256>>>();
    stats_kernel<<<Rc, 256>>>(adj);
    pv_mma<<<Rc / 64, 256, SMEM_PV>>>(adj, out);
}